// round 1
// baseline (speedup 1.0000x reference)
#include <cuda_runtime.h>

#define NC 19
#define HH 512
#define WW 512
#define TILE 16
#define HPIX 18                 // tile + 1-pixel halo
#define NPIX (HPIX * HPIX)      // 324
#define PSTR 20                 // padded class stride for float4 loads
#define LOG_EPS (-9.210340371976182f)   // logf(1e-4)
#define MARGIN 3.0f

// ---------------- global accumulators / precomputed class weights ----------------
__device__ double g_esum;
__device__ double g_nesum;
__device__ unsigned long long g_ecnt;
__device__ unsigned long long g_necnt;
__device__ float g_we[NC];
__device__ float g_wne[NC];

__global__ void aaf_init(const float* __restrict__ w_edge,
                         const float* __restrict__ w_not_edge) {
    int c = threadIdx.x;
    if (c == 0) { g_esum = 0.0; g_nesum = 0.0; g_ecnt = 0ull; g_necnt = 0ull; }
    if (c < NC) {
        // w shape (1,1,1,19,1,3): softmax over last dim, take [...,0]
        const float* r = w_edge + c * 3;
        float m = fmaxf(r[0], fmaxf(r[1], r[2]));
        float e0 = __expf(r[0] - m), e1 = __expf(r[1] - m), e2 = __expf(r[2] - m);
        g_we[c] = e0 / (e0 + e1 + e2);
        r = w_not_edge + c * 3;
        m = fmaxf(r[0], fmaxf(r[1], r[2]));
        e0 = __expf(r[0] - m); e1 = __expf(r[1] - m); e2 = __expf(r[2] - m);
        g_wne[c] = e0 / (e0 + e1 + e2);
    }
}

// ---------------- fused main kernel ----------------
__global__ __launch_bounds__(256, 2)
void aaf_main(const float* __restrict__ preds, const int* __restrict__ targets) {
    extern __shared__ float sm[];
    float* sp   = sm;                       // [NPIX][PSTR]  prob (padded)
    float* slp  = sp + NPIX * PSTR;         // [NPIX][NC]    log(clip(p))
    float* slnp = slp + NPIX * NC;          // [NPIX][NC]    log(clip(1-p))
    float* sE   = slnp + NPIX * NC;         // [NPIX]        sum_c ppc*lp + nppc*lnp
    int*   slab = (int*)(sE + NPIX);        // [NPIX]        labels (-1 = OOB)

    const int n   = blockIdx.z;
    const int ty0 = blockIdx.y * TILE;
    const int tx0 = blockIdx.x * TILE;
    const float* __restrict__ predn = preds + (size_t)n * NC * 64 * 64;
    const int*   __restrict__ labn  = targets + (size_t)n * HH * WW;

    // ---- Phase 1: per-(halo)pixel prob / logs / entropy-sum ----
    for (int i = threadIdx.x; i < NPIX; i += 256) {
        int ly = i / HPIX, lx = i - ly * HPIX;
        int gy = ty0 + ly - 1, gx = tx0 + lx - 1;
        if (gy < 0 || gy >= HH || gx < 0 || gx >= WW) { slab[i] = -1; continue; }
        slab[i] = labn[gy * WW + gx];

        // align_corners bilinear source coords, 512 -> 64: scale (64-1)/(512-1)
        const float scale = 63.0f / 511.0f;
        float fy = gy * scale, fx = gx * scale;
        int y0 = (int)fy, x0 = (int)fx;
        float wy = fy - (float)y0, wx = fx - (float)x0;
        int dx = (x0 < 63) ? 1 : 0;
        int dy = ((y0 < 63) ? 1 : 0) * 64;
        const float* b00 = predn + y0 * 64 + x0;

        float* prow = sp + i * PSTR;
        float vmax = -1e30f;
        #pragma unroll
        for (int c = 0; c < NC; c++) {
            const float* b = b00 + c * 4096;
            float a = b[0], bb = b[dx], cc = b[dy], dd = b[dy + dx];
            float top = a + wx * (bb - a);
            float bot = cc + wx * (dd - cc);
            float v = top + wy * (bot - top);
            prow[c] = v;
            vmax = fmaxf(vmax, v);
        }
        float s = 0.f;
        #pragma unroll
        for (int c = 0; c < NC; c++) {
            float e = __expf(prow[c] - vmax);
            prow[c] = e;
            s += e;
        }
        float inv = 1.0f / s;
        float E = 0.f;
        #pragma unroll
        for (int c = 0; c < NC; c++) {
            float p = prow[c] * inv;
            prow[c] = p;
            float ppc  = fmaxf(p, 1e-4f);
            float nppc = fmaxf(1.0f - p, 1e-4f);
            float lp  = __logf(ppc);
            float lnp = __logf(nppc);
            slp[i * NC + c]  = lp;
            slnp[i * NC + c] = lnp;
            E = fmaf(ppc, lp, E);
            E = fmaf(nppc, lnp, E);
        }
        sE[i] = E;
    }
    __syncthreads();

    // ---- Phase 2: per-center-pixel 8-neighbor accumulation ----
    const int lx = threadIdx.x & (TILE - 1);
    const int ly = threadIdx.x >> 4;
    const int gy = ty0 + ly, gx = tx0 + lx;
    const int ci = (ly + 1) * HPIX + (lx + 1);
    const int lc = slab[ci];

    float lpc[NC], lnpc[NC];
    #pragma unroll
    for (int c = 0; c < NC; c++) {
        lpc[c]  = slp[ci * NC + c];
        lnpc[c] = slnp[ci * NC + c];
    }

    float esum = 0.f, nesum = 0.f;
    int ecnt = 0, necnt = 0;

    if ((unsigned)lc < NC) {  // center not ignored
        const float we  = g_we[lc];
        const float wne = g_wne[lc];
        const float lpc_lc  = slp[ci * NC + lc];   // dynamic index -> smem
        const float lnpc_lc = slnp[ci * NC + lc];

        const int OY[8] = {-1, -1, -1, 0, 0, 1, 1, 1};
        const int OX[8] = {-1,  0,  1,-1, 1,-1, 0, 1};
        #pragma unroll
        for (int k = 0; k < 8; k++) {
            const int oy = OY[k], ox = OX[k];
            // gate: "minus" neighbor (reference shifts ignore mask by -offset, pad=True)
            int my = gy - oy, mx = gx - ox;
            if (my < 0 || my >= HH || mx < 0 || mx >= WW) continue;
            int mlab = slab[(ly + 1 - oy) * HPIX + (lx + 1 - ox)];
            if ((unsigned)mlab >= NC) continue;

            int py = gy + oy, px = gx + ox;
            bool plus_in = (py >= 0) && (py < HH) && (px >= 0) && (px < WW);
            if (!plus_in) {
                // plus-neighbor OOB: ohl padded 255 != one-hot -> ALL classes edge,
                // prob padded 0 -> ppc=1e-4, nppc=1.0
                float sB = 0.f;
                #pragma unroll
                for (int c = 0; c < NC; c++) {
                    float kld = fmaf(1e-4f, (LOG_EPS - lpc[c]), -lnpc[c]);
                    sB += fmaxf(0.f, MARGIN - kld);
                }
                esum = fmaf(we, sB, esum);
                ecnt += NC;
                continue;
            }

            const int ni = (ly + 1 + oy) * HPIX + (lx + 1 + ox);
            const int ln = slab[ni];
            const float* pn = sp + ni * PSTR;

            if ((unsigned)ln >= NC) {
                // in-bounds ignored neighbor: all classes edge with real probs
                float sB = 0.f;
                #pragma unroll
                for (int c = 0; c < NC; c++) {
                    float p = pn[c];
                    float ppc  = fmaxf(p, 1e-4f);
                    float nppc = fmaxf(1.f - p, 1e-4f);
                    float kld = ppc * (slp[ni * NC + c] - lpc[c])
                              + nppc * (slnp[ni * NC + c] - lnpc[c]);
                    sB += fmaxf(0.f, MARGIN - kld);
                }
                esum = fmaf(we, sB, esum);
                ecnt += NC;
                continue;
            }

            // Normal path: S = sum_c kld[c] = E_nb - sum_c(ppc_nb*lp_c + nppc_nb*lnp_c)
            float acc = 0.f;
            const float4* pv = (const float4*)pn;
            #pragma unroll
            for (int q = 0; q < 4; q++) {
                float4 v = pv[q];
                acc = fmaf(fmaxf(v.x, 1e-4f),       lpc[4 * q + 0], acc);
                acc = fmaf(fmaxf(1.f - v.x, 1e-4f), lnpc[4 * q + 0], acc);
                acc = fmaf(fmaxf(v.y, 1e-4f),       lpc[4 * q + 1], acc);
                acc = fmaf(fmaxf(1.f - v.y, 1e-4f), lnpc[4 * q + 1], acc);
                acc = fmaf(fmaxf(v.z, 1e-4f),       lpc[4 * q + 2], acc);
                acc = fmaf(fmaxf(1.f - v.z, 1e-4f), lnpc[4 * q + 2], acc);
                acc = fmaf(fmaxf(v.w, 1e-4f),       lpc[4 * q + 3], acc);
                acc = fmaf(fmaxf(1.f - v.w, 1e-4f), lnpc[4 * q + 3], acc);
            }
            #pragma unroll
            for (int c = 16; c < NC; c++) {
                float p = pn[c];
                acc = fmaf(fmaxf(p, 1e-4f),       lpc[c], acc);
                acc = fmaf(fmaxf(1.f - p, 1e-4f), lnpc[c], acc);
            }
            float S = sE[ni] - acc;

            // kld at center's class (dynamic index -> smem)
            float pcl = pn[lc];
            float kcl = fmaxf(pcl, 1e-4f)       * (slp[ni * NC + lc] - lpc_lc)
                      + fmaxf(1.f - pcl, 1e-4f) * (slnp[ni * NC + lc] - lnpc_lc);

            if (ln == lc) {
                nesum = fmaf(wne, S, nesum);
                necnt += NC;
            } else {
                float pln = pn[ln];
                float kln = fmaxf(pln, 1e-4f)       * (slp[ni * NC + ln] - slp[ci * NC + ln])
                          + fmaxf(1.f - pln, 1e-4f) * (slnp[ni * NC + ln] - slnp[ci * NC + ln]);
                nesum = fmaf(wne, S - kcl - kln, nesum);
                necnt += NC - 2;
                esum = fmaf(we, fmaxf(0.f, MARGIN - kcl) + fmaxf(0.f, MARGIN - kln), esum);
                ecnt += 2;
            }
        }
    }

    // ---- block reduction + global atomics ----
    #pragma unroll
    for (int o = 16; o > 0; o >>= 1) {
        esum  += __shfl_down_sync(0xffffffffu, esum, o);
        nesum += __shfl_down_sync(0xffffffffu, nesum, o);
        ecnt  += __shfl_down_sync(0xffffffffu, ecnt, o);
        necnt += __shfl_down_sync(0xffffffffu, necnt, o);
    }
    __shared__ float red_e[8], red_ne[8];
    __shared__ int red_ec[8], red_nc[8];
    int wid = threadIdx.x >> 5, lid = threadIdx.x & 31;
    if (lid == 0) { red_e[wid] = esum; red_ne[wid] = nesum; red_ec[wid] = ecnt; red_nc[wid] = necnt; }
    __syncthreads();
    if (wid == 0) {
        float be  = (lid < 8) ? red_e[lid]  : 0.f;
        float bne = (lid < 8) ? red_ne[lid] : 0.f;
        int bec = (lid < 8) ? red_ec[lid] : 0;
        int bnc = (lid < 8) ? red_nc[lid] : 0;
        #pragma unroll
        for (int o = 4; o > 0; o >>= 1) {
            be  += __shfl_down_sync(0xffffffffu, be, o);
            bne += __shfl_down_sync(0xffffffffu, bne, o);
            bec += __shfl_down_sync(0xffffffffu, bec, o);
            bnc += __shfl_down_sync(0xffffffffu, bnc, o);
        }
        if (lid == 0) {
            atomicAdd(&g_esum, (double)be);
            atomicAdd(&g_nesum, (double)bne);
            atomicAdd(&g_ecnt, (unsigned long long)bec);
            atomicAdd(&g_necnt, (unsigned long long)bnc);
        }
    }
}

__global__ void aaf_fin(float* __restrict__ out) {
    double e  = g_esum  / (double)(g_ecnt  > 0 ? g_ecnt  : 1ull);
    double ne = g_nesum / (double)(g_necnt > 0 ? g_necnt : 1ull);
    out[0] = (float)((e + ne) * 0.01);
}

// ---------------- launch ----------------
extern "C" void kernel_launch(void* const* d_in, const int* in_sizes, int n_in,
                              void* d_out, int out_size) {
    const float* preds      = (const float*)d_in[0];
    const int*   targets    = (const int*)d_in[1];
    const float* w_edge     = (const float*)d_in[2];
    const float* w_not_edge = (const float*)d_in[3];

    int nb = in_sizes[1] / (HH * WW);   // batch size from targets element count

    size_t smem = (size_t)(NPIX * PSTR + 2 * NPIX * NC + NPIX) * sizeof(float)
                + (size_t)NPIX * sizeof(int);   // 77,760 bytes
    cudaFuncSetAttribute(aaf_main, cudaFuncAttributeMaxDynamicSharedMemorySize, (int)smem);

    aaf_init<<<1, 32>>>(w_edge, w_not_edge);
    dim3 grid(WW / TILE, HH / TILE, nb);
    aaf_main<<<grid, 256, smem>>>(preds, targets);
    aaf_fin<<<1, 1>>>((float*)d_out);
}

// round 2
// speedup vs baseline: 1.1360x; 1.1360x over previous
#include <cuda_runtime.h>

#define NC 19
#define HH 512
#define WW 512
#define TILE 16
#define HPIX 18                 // tile + 1-pixel halo
#define NPIX 324                // 18*18
#define LOG_EPS (-9.210340371976182f)   // logf(1e-4)
#define MARGIN 3.0f
#define MAXBLK 8192

// smem float offsets
#define OFF_SPN   0                       // NPIX*19 float2 = 12312 floats
#define OFF_PATCH 12312                   // 19*25 = 475 (pad 480)
#define OFF_SE    12792                   // 324
#define OFF_SWE   13116                   // 19
#define OFF_SWNE  13135                   // 19
#define OFF_SLAB  13156                   // 324 ints
#define SMEM_FLOATS 13480                 // 53,920 bytes

// ---------------- per-block partial outputs (no init kernel needed) ----------------
__device__ float g_pe[MAXBLK];
__device__ float g_pne[MAXBLK];
__device__ int   g_pec[MAXBLK];
__device__ int   g_pnec[MAXBLK];

__device__ __forceinline__ unsigned long long pack2(float a, float b) {
    unsigned long long r;
    asm("mov.b64 %0, {%1,%2};" : "=l"(r) : "f"(a), "f"(b));
    return r;
}
__device__ __forceinline__ void unpack2(unsigned long long v, float& a, float& b) {
    asm("mov.b64 {%0,%1}, %2;" : "=f"(a), "=f"(b) : "l"(v));
}
#define FMA2(acc, a, b) asm("fma.rn.f32x2 %0, %1, %2, %0;" : "+l"(acc) : "l"(a), "l"(b))

// ---- phase-1 per-pixel: bilinear (from smem patch) + softmax + clipped pair + E ----
template<bool KEEP>
__device__ __forceinline__ void do_pixel(int i, int gy, int gx,
    int sy_base, int sx_base, const float* __restrict__ spatch,
    float2* __restrict__ spn, float* __restrict__ sE, unsigned long long* l2)
{
    const float scale = 63.0f / 511.0f;
    float fy = gy * scale, fx = gx * scale;
    int y0 = (int)fy, x0 = (int)fx;
    float wy = fy - (float)y0, wx = fx - (float)x0;
    const float* pb0 = spatch + (y0 - sy_base) * 5 + (x0 - sx_base);

    float pr[NC];
    float vmax = -1e30f;
#pragma unroll
    for (int c = 0; c < NC; c++) {
        const float* pb = pb0 + c * 25;
        float a = pb[0], b = pb[1], cc = pb[5], d = pb[6];
        float top = a + wx * (b - a);
        float bot = cc + wx * (d - cc);
        float v = top + wy * (bot - top);
        pr[c] = v;
        vmax = fmaxf(vmax, v);
    }
    float s = 0.f;
#pragma unroll
    for (int c = 0; c < NC; c++) { float e = __expf(pr[c] - vmax); pr[c] = e; s += e; }
    float inv = 1.0f / s;
    float E = 0.f;
    float2* orow = spn + i * NC;
#pragma unroll
    for (int c = 0; c < NC; c++) {
        float p = pr[c] * inv;
        float ppc  = fmaxf(p, 1e-4f);
        float nppc = fmaxf(1.0f - p, 1e-4f);
        float lp = __logf(ppc), lnp = __logf(nppc);
        orow[c] = make_float2(ppc, nppc);
        E = fmaf(ppc, lp, fmaf(nppc, lnp, E));
        if (KEEP) l2[c] = pack2(lp, lnp);
    }
    sE[i] = E;
}

// ---------------- fused main kernel ----------------
__global__ __launch_bounds__(256, 3)
void aaf_main(const float* __restrict__ preds, const int* __restrict__ targets,
              const float* __restrict__ w_edge, const float* __restrict__ w_not_edge)
{
    extern __shared__ float sm[];
    float2* spn    = (float2*)sm;
    float*  spatch = sm + OFF_PATCH;
    float*  sE     = sm + OFF_SE;
    float*  swe    = sm + OFF_SWE;
    float*  swne   = sm + OFF_SWNE;
    int*    slab   = (int*)(sm + OFF_SLAB);

    const int tid = threadIdx.x;
    const int n   = blockIdx.z;
    const int ty0 = blockIdx.y * TILE;
    const int tx0 = blockIdx.x * TILE;
    const float* __restrict__ predn = preds + (size_t)n * NC * 64 * 64;
    const int*   __restrict__ labn  = targets + (size_t)n * HH * WW;

    // source patch base (covers gy in [ty0-1, ty0+16] clamped)
    const float scale = 63.0f / 511.0f;
    const int gy_min = max(ty0 - 1, 0), gx_min = max(tx0 - 1, 0);
    const int sy_base = (int)(gy_min * scale);
    const int sx_base = (int)(gx_min * scale);

    // cooperative: 5x5x19 source patch -> smem (clamped replicate at borders)
    for (int i = tid; i < NC * 25; i += 256) {
        int c = i / 25, r = i - c * 25;
        int sy = min(sy_base + r / 5, 63);
        int sx = min(sx_base + (r - (r / 5) * 5), 63);
        spatch[i] = predn[c * 4096 + sy * 64 + sx];
    }
    // class weights: softmax over 3, index 0
    if (tid < NC) {
        const float* r = w_edge + tid * 3;
        float m = fmaxf(r[0], fmaxf(r[1], r[2]));
        float e0 = __expf(r[0] - m), e1 = __expf(r[1] - m), e2 = __expf(r[2] - m);
        swe[tid] = e0 / (e0 + e1 + e2);
        r = w_not_edge + tid * 3;
        m = fmaxf(r[0], fmaxf(r[1], r[2]));
        e0 = __expf(r[0] - m); e1 = __expf(r[1] - m); e2 = __expf(r[2] - m);
        swne[tid] = e0 / (e0 + e1 + e2);
    }
    __syncthreads();

    // ---- phase 1a: each thread does its OWN center pixel, keeps packed logs in regs
    const int lxc = tid & (TILE - 1);
    const int lyc = tid >> 4;
    const int gy = ty0 + lyc, gx = tx0 + lxc;
    const int ci = (lyc + 1) * HPIX + (lxc + 1);

    unsigned long long l2[NC];
    slab[ci] = labn[gy * WW + gx];
    do_pixel<true>(ci, gy, gx, sy_base, sx_base, spatch, spn, sE, l2);

    // ---- phase 1b: ring (68 halo pixels) by threads 0..67
    if (tid < 68) {
        int ly, lx;
        if (tid < 18)      { ly = 0;  lx = tid; }
        else if (tid < 36) { ly = 17; lx = tid - 18; }
        else { int u = tid - 36; ly = 1 + (u >> 1); lx = (u & 1) ? 17 : 0; }
        int i = ly * HPIX + lx;
        int ry = ty0 + ly - 1, rx = tx0 + lx - 1;
        if (ry < 0 || ry >= HH || rx < 0 || rx >= WW) {
            slab[i] = -1;
        } else {
            slab[i] = labn[ry * WW + rx];
            do_pixel<false>(i, ry, rx, sy_base, sx_base, spatch, spn, sE, (unsigned long long*)0);
        }
    }
    __syncthreads();

    // ---- phase 2: 8-neighbor accumulation ----
    const int lc = slab[ci];
    float esum = 0.f, nesum = 0.f;
    int ecnt = 0, necnt = 0;

    if ((unsigned)lc < NC) {
        const float we  = swe[lc];
        const float wne = swne[lc];
        float2 pc_lc = spn[ci * NC + lc];
        const float lp_c_lc  = __logf(pc_lc.x);
        const float lnp_c_lc = __logf(pc_lc.y);

        const int OY[8] = {-1, -1, -1, 0, 0, 1, 1, 1};
        const int OX[8] = {-1,  0,  1,-1, 1,-1, 0, 1};
#pragma unroll
        for (int k = 0; k < 8; k++) {
            const int oy = OY[k], ox = OX[k];
            // gate: minus-neighbor (reference shifts ignore mask by -offset, pad=ignored)
            int my = gy - oy, mx = gx - ox;
            if (my < 0 || my >= HH || mx < 0 || mx >= WW) continue;
            int mlab = slab[ci - oy * HPIX - ox];
            if ((unsigned)mlab >= NC) continue;

            int py = gy + oy, px = gx + ox;
            if (py < 0 || py >= HH || px < 0 || px >= WW) {
                // plus-neighbor OOB: all classes edge; padded prob 0 -> ppc=1e-4, nppc=1
                float sB = 0.f;
#pragma unroll
                for (int c = 0; c < NC; c++) {
                    float lp, lnp; unpack2(l2[c], lp, lnp);
                    float kld = fmaf(1e-4f, LOG_EPS - lp, -lnp);
                    sB += fmaxf(0.f, MARGIN - kld);
                }
                esum = fmaf(we, sB, esum);
                ecnt += NC;
                continue;
            }

            const int ni = ci + oy * HPIX + ox;
            const int ln = slab[ni];
            const unsigned long long* rp = (const unsigned long long*)(spn + ni * NC);

            if ((unsigned)ln >= NC) {
                // in-bounds ignored neighbor: all classes edge with real probs (rare)
                const float2* prow = spn + ni * NC;
                float sB = 0.f;
#pragma unroll 1
                for (int c = 0; c < NC; c++) {
                    float lp, lnp; unpack2(l2[c], lp, lnp);
                    float2 q = prow[c];
                    float kld = q.x * (__logf(q.x) - lp) + q.y * (__logf(q.y) - lnp);
                    sB += fmaxf(0.f, MARGIN - kld);
                }
                esum = fmaf(we, sB, esum);
                ecnt += NC;
                continue;
            }

            // normal path: S = E_nb - sum_c (ppc_nb*lp_c + nppc_nb*lnp_c), via f32x2 FMA
            unsigned long long a0 = 0ull, a1 = 0ull;
#pragma unroll
            for (int c = 0; c < 18; c += 2) {
                FMA2(a0, rp[c],     l2[c]);
                FMA2(a1, rp[c + 1], l2[c + 1]);
            }
            FMA2(a0, rp[18], l2[18]);
            float d0, d1, d2, d3;
            unpack2(a0, d0, d1);
            unpack2(a1, d2, d3);
            float S = sE[ni] - ((d0 + d1) + (d2 + d3));

            if (ln == lc) {
                nesum = fmaf(wne, S, nesum);
                necnt += NC;
            } else {
                // kld at center's class lc
                float2 pn_lc = spn[ni * NC + lc];
                float kcl = pn_lc.x * (__logf(pn_lc.x) - lp_c_lc)
                          + pn_lc.y * (__logf(pn_lc.y) - lnp_c_lc);
                // kld at neighbor's class ln
                float2 pn_ln = spn[ni * NC + ln];
                float2 pc_ln = spn[ci * NC + ln];
                float kln = pn_ln.x * (__logf(pn_ln.x) - __logf(pc_ln.x))
                          + pn_ln.y * (__logf(pn_ln.y) - __logf(pc_ln.y));
                nesum = fmaf(wne, S - kcl - kln, nesum);
                necnt += NC - 2;
                esum = fmaf(we, fmaxf(0.f, MARGIN - kcl) + fmaxf(0.f, MARGIN - kln), esum);
                ecnt += 2;
            }
        }
    }

    // ---- block reduction, write per-block partial ----
#pragma unroll
    for (int o = 16; o > 0; o >>= 1) {
        esum  += __shfl_down_sync(0xffffffffu, esum, o);
        nesum += __shfl_down_sync(0xffffffffu, nesum, o);
        ecnt  += __shfl_down_sync(0xffffffffu, ecnt, o);
        necnt += __shfl_down_sync(0xffffffffu, necnt, o);
    }
    __shared__ float red_e[8], red_ne[8];
    __shared__ int red_ec[8], red_nc[8];
    int wid = tid >> 5, lid = tid & 31;
    if (lid == 0) { red_e[wid] = esum; red_ne[wid] = nesum; red_ec[wid] = ecnt; red_nc[wid] = necnt; }
    __syncthreads();
    if (wid == 0) {
        float be  = (lid < 8) ? red_e[lid]  : 0.f;
        float bne = (lid < 8) ? red_ne[lid] : 0.f;
        int bec = (lid < 8) ? red_ec[lid] : 0;
        int bnc = (lid < 8) ? red_nc[lid] : 0;
#pragma unroll
        for (int o = 4; o > 0; o >>= 1) {
            be  += __shfl_down_sync(0xffffffffu, be, o);
            bne += __shfl_down_sync(0xffffffffu, bne, o);
            bec += __shfl_down_sync(0xffffffffu, bec, o);
            bnc += __shfl_down_sync(0xffffffffu, bnc, o);
        }
        if (lid == 0) {
            int bid = (blockIdx.z * gridDim.y + blockIdx.y) * gridDim.x + blockIdx.x;
            g_pe[bid] = be; g_pne[bid] = bne; g_pec[bid] = bec; g_pnec[bid] = bnc;
        }
    }
}

// ---------------- finalize: reduce per-block partials ----------------
__global__ void aaf_fin(float* __restrict__ out, int nblocks) {
    int tid = threadIdx.x;
    double e = 0.0, ne = 0.0;
    long long ec = 0, nec = 0;
    for (int i = tid; i < nblocks; i += 256) {
        e += (double)g_pe[i]; ne += (double)g_pne[i];
        ec += g_pec[i]; nec += g_pnec[i];
    }
#pragma unroll
    for (int o = 16; o > 0; o >>= 1) {
        e   += __shfl_down_sync(0xffffffffu, e, o);
        ne  += __shfl_down_sync(0xffffffffu, ne, o);
        ec  += __shfl_down_sync(0xffffffffu, ec, o);
        nec += __shfl_down_sync(0xffffffffu, nec, o);
    }
    __shared__ double se[8], sne[8];
    __shared__ long long sec[8], snec[8];
    int wid = tid >> 5, lid = tid & 31;
    if (lid == 0) { se[wid] = e; sne[wid] = ne; sec[wid] = ec; snec[wid] = nec; }
    __syncthreads();
    if (tid == 0) {
        double te = 0, tne = 0; long long tec = 0, tnec = 0;
        for (int i = 0; i < 8; i++) { te += se[i]; tne += sne[i]; tec += sec[i]; tnec += snec[i]; }
        double em  = te  / (double)(tec  > 0 ? tec  : 1);
        double nem = tne / (double)(tnec > 0 ? tnec : 1);
        out[0] = (float)((em + nem) * 0.01);
    }
}

// ---------------- launch ----------------
extern "C" void kernel_launch(void* const* d_in, const int* in_sizes, int n_in,
                              void* d_out, int out_size) {
    const float* preds      = (const float*)d_in[0];
    const int*   targets    = (const int*)d_in[1];
    const float* w_edge     = (const float*)d_in[2];
    const float* w_not_edge = (const float*)d_in[3];

    int nb = in_sizes[1] / (HH * WW);
    int smem = SMEM_FLOATS * 4;   // 53,920 bytes
    cudaFuncSetAttribute(aaf_main, cudaFuncAttributeMaxDynamicSharedMemorySize, smem);

    dim3 grid(WW / TILE, HH / TILE, nb);
    aaf_main<<<grid, 256, smem>>>(preds, targets, w_edge, w_not_edge);
    aaf_fin<<<1, 256>>>((float*)d_out, (int)(grid.x * grid.y * grid.z));
}